// round 5
// baseline (speedup 1.0000x reference)
#include <cuda_runtime.h>
#include <math.h>

#define NN 100000
#define EE 800000
#define DOUT 47
#define BCAP 64

// Scratch (allocation-free rule: static device globals)
__device__ float g_h[(size_t)NN * 64];
__device__ float g_agg[(size_t)NN * 64];
__device__ int   g_deg[NN];
__device__ int   g_bkt[(size_t)NN * BCAP];
__device__ int   g_idx64;

// ---------------------------------------------------------------------------
// Packed fp32x2 FMA (Blackwell FFMA2 — only reachable via PTX)
// ---------------------------------------------------------------------------
__device__ __forceinline__ void ffma2(unsigned long long& acc,
                                      unsigned long long a,
                                      unsigned long long b) {
    asm("fma.rn.f32x2 %0, %1, %2, %0;" : "+l"(acc) : "l"(a), "l"(b));
}
__device__ __forceinline__ unsigned long long pack2(float x) {
    unsigned long long r;
    asm("mov.b64 %0, {%1, %2};" : "=l"(r) : "f"(x), "f"(x));
    return r;
}

// ---------------------------------------------------------------------------
// zero degree array + (block 0) detect edge_index dtype (int64 vs int32)
// ---------------------------------------------------------------------------
__global__ void zero_detect_kernel(const void* ei) {
    int i = blockIdx.x * blockDim.x + threadIdx.x;
    if (i < NN) g_deg[i] = 0;
    if (blockIdx.x == 0) {
        __shared__ int bad;
        if (threadIdx.x == 0) bad = 0;
        __syncthreads();
        const long long* p = (const long long*)ei;
        for (int j = threadIdx.x; j < 4096; j += blockDim.x) {
            long long v = p[j];
            if (v < 0 || v >= NN) bad = 1;
        }
        __syncthreads();
        if (threadIdx.x == 0) g_idx64 = bad ? 0 : 1;
    }
}

// ---------------------------------------------------------------------------
// Bucket fill: bkt[dst][pos++] = src
// ---------------------------------------------------------------------------
__global__ void bucket_fill_kernel(const void* ei) {
    int e = blockIdx.x * blockDim.x + threadIdx.x;
    if (e >= EE) return;
    int src, dst;
    if (g_idx64) {
        const long long* p = (const long long*)ei;
        src = (int)p[e];
        dst = (int)p[EE + e];
    } else {
        const int* p = (const int*)ei;
        src = p[e];
        dst = p[EE + e];
    }
    int pos = atomicAdd(&g_deg[dst], 1);
    if (pos < BCAP) g_bkt[(size_t)dst * BCAP + pos] = src;
}

// ---------------------------------------------------------------------------
// GEMM (FFMA2): out[N, DP] = in[N, 64] @ W[64, wcols] (zero-padded to DP).
// 128 rows/block, 256 threads. Thread: 2 rows x NC cols, packed f32x2 accs.
// ---------------------------------------------------------------------------
template <int DP>   // 64 or 48
__global__ void gemm_kernel(const float* __restrict__ in,
                            const float* __restrict__ W,
                            float* __restrict__ out, int wcols) {
    constexpr int NC = DP / 4;     // cols per thread (16 / 12)
    constexpr int NU = NC / 4;     // ulonglong2 per row-chunk (4 / 3)
    constexpr int NA = NC / 2;     // b64 accumulators per row (8 / 6)
    extern __shared__ float4 smem[];
    float4* xs = smem;             // 128 rows, stride 17 float4
    float4* ws = smem + 128 * 17;  // 64 rows x DP/4 float4

    int tid  = threadIdx.x;
    int row0 = blockIdx.x * 128;

    float* wsf = (float*)ws;
    for (int i = tid; i < 64 * DP; i += 256) {
        int k = i / DP, c = i - k * DP;
        wsf[i] = (c < wcols) ? W[k * wcols + c] : 0.f;
    }
    for (int i = tid; i < 128 * 16; i += 256) {
        int r = i >> 4, c = i & 15;
        int gr = row0 + r;
        xs[r * 17 + c] = (gr < NN) ? ((const float4*)in)[(size_t)gr * 16 + c]
                                   : make_float4(0.f, 0.f, 0.f, 0.f);
    }
    __syncthreads();

    int r  = tid >> 2;
    int cg = tid & 3;
    unsigned long long a0[NA], a1[NA];
#pragma unroll
    for (int j = 0; j < NA; j++) { a0[j] = 0ULL; a1[j] = 0ULL; }

    const float4* xr0 = &xs[r * 17];
    const float4* xr1 = &xs[(r + 64) * 17];
    const char* wbase = (const char*)wsf + (size_t)cg * NC * 4;

#pragma unroll 4
    for (int kk = 0; kk < 16; kk++) {
        float4 xa = xr0[kk], xb = xr1[kk];
        float xaf[4] = {xa.x, xa.y, xa.z, xa.w};
        float xbf[4] = {xb.x, xb.y, xb.z, xb.w};
#pragma unroll
        for (int q = 0; q < 4; q++) {
            int k = kk * 4 + q;
            const ulonglong2* wrow = (const ulonglong2*)(wbase + (size_t)k * DP * 4);
            unsigned long long xx0 = pack2(xaf[q]);
            unsigned long long xx1 = pack2(xbf[q]);
#pragma unroll
            for (int j = 0; j < NU; j++) {
                ulonglong2 w2 = wrow[j];
                ffma2(a0[2 * j],     xx0, w2.x);
                ffma2(a0[2 * j + 1], xx0, w2.y);
                ffma2(a1[2 * j],     xx1, w2.x);
                ffma2(a1[2 * j + 1], xx1, w2.y);
            }
        }
    }

    int gr0 = row0 + r, gr1 = gr0 + 64;
    ulonglong2* o2 = (ulonglong2*)out;
    constexpr int DQ = DP / 4;
    if (gr0 < NN) {
#pragma unroll
        for (int j = 0; j < NU; j++)
            o2[(size_t)gr0 * DQ + cg * NU + j] =
                make_ulonglong2(a0[2 * j], a0[2 * j + 1]);
    }
    if (gr1 < NN) {
#pragma unroll
        for (int j = 0; j < NU; j++)
            o2[(size_t)gr1 * DQ + cg * NU + j] =
                make_ulonglong2(a1[2 * j], a1[2 * j + 1]);
    }
}

// ---------------------------------------------------------------------------
// Gather: out[n] = epilogue(bias + sum_{e in bkt[n]} h[src[e]]).
// 16 lanes per node, lane = one float4 chunk. Indices front-batched via int4
// loads (MLP ~8-10). Epilogue: ReLU store, or fused log_softmax (LSM).
// ---------------------------------------------------------------------------
template <int CH, bool LSM>
__global__ void gather_kernel(const float* __restrict__ h,
                              const float* __restrict__ bias, int bcols,
                              float* __restrict__ outp) {
    int t = blockIdx.x * blockDim.x + threadIdx.x;
    int n = t >> 4;
    int ln = t & 15;
    if (n >= NN) return;

    const bool act = (ln < CH);
    float4 a = make_float4(0.f, 0.f, 0.f, 0.f);
    float4 b = a;
    if (act) {
        int c = ln * 4;
        a.x = bias[c];
        a.y = bias[c + 1];
        a.z = bias[c + 2];
        a.w = (c + 3 < bcols) ? bias[c + 3] : 0.f;
    }

    int deg = min(g_deg[n], BCAP);
    const int* bp = &g_bkt[(size_t)n * BCAP];
    const float4* h4 = (const float4*)h;

    int e = 0;
    // 8-edge batches: two independent int4 index loads, then 8 independent
    // float4 gathers (front-batched -> deep L1tex/LTS queue occupancy).
    for (; e + 8 <= deg; e += 8) {
        int4 i0 = *(const int4*)(bp + e);
        int4 i1 = *(const int4*)(bp + e + 4);
        if (act) {
            float4 v0 = h4[(size_t)i0.x * CH + ln];
            float4 v1 = h4[(size_t)i0.y * CH + ln];
            float4 v2 = h4[(size_t)i0.z * CH + ln];
            float4 v3 = h4[(size_t)i0.w * CH + ln];
            float4 v4 = h4[(size_t)i1.x * CH + ln];
            float4 v5 = h4[(size_t)i1.y * CH + ln];
            float4 v6 = h4[(size_t)i1.z * CH + ln];
            float4 v7 = h4[(size_t)i1.w * CH + ln];
            a.x += (v0.x + v1.x) + (v2.x + v3.x);
            a.y += (v0.y + v1.y) + (v2.y + v3.y);
            a.z += (v0.z + v1.z) + (v2.z + v3.z);
            a.w += (v0.w + v1.w) + (v2.w + v3.w);
            b.x += (v4.x + v5.x) + (v6.x + v7.x);
            b.y += (v4.y + v5.y) + (v6.y + v7.y);
            b.z += (v4.z + v5.z) + (v6.z + v7.z);
            b.w += (v4.w + v5.w) + (v6.w + v7.w);
        }
    }
    if (e + 4 <= deg) {
        int4 i0 = *(const int4*)(bp + e);
        if (act) {
            float4 v0 = h4[(size_t)i0.x * CH + ln];
            float4 v1 = h4[(size_t)i0.y * CH + ln];
            float4 v2 = h4[(size_t)i0.z * CH + ln];
            float4 v3 = h4[(size_t)i0.w * CH + ln];
            a.x += (v0.x + v1.x) + (v2.x + v3.x);
            a.y += (v0.y + v1.y) + (v2.y + v3.y);
            a.z += (v0.z + v1.z) + (v2.z + v3.z);
            a.w += (v0.w + v1.w) + (v2.w + v3.w);
        }
        e += 4;
    }
    // 0-3 leftover edges: load indices first, then gathers
    {
        int r = deg - e;
        int s0 = (r > 0) ? bp[e]     : 0;
        int s1 = (r > 1) ? bp[e + 1] : 0;
        int s2 = (r > 2) ? bp[e + 2] : 0;
        if (act) {
            if (r > 0) {
                float4 v = h4[(size_t)s0 * CH + ln];
                a.x += v.x; a.y += v.y; a.z += v.z; a.w += v.w;
            }
            if (r > 1) {
                float4 v = h4[(size_t)s1 * CH + ln];
                b.x += v.x; b.y += v.y; b.z += v.z; b.w += v.w;
            }
            if (r > 2) {
                float4 v = h4[(size_t)s2 * CH + ln];
                a.x += v.x; a.y += v.y; a.z += v.z; a.w += v.w;
            }
        }
    }
    a.x += b.x; a.y += b.y; a.z += b.z; a.w += b.w;

    if (!LSM) {
        a.x = fmaxf(a.x, 0.f); a.y = fmaxf(a.y, 0.f);
        a.z = fmaxf(a.z, 0.f); a.w = fmaxf(a.w, 0.f);
        if (act) ((float4*)outp)[(size_t)n * CH + ln] = a;
    } else {
        // CH == 12, 47 valid columns.
        float e0 = a.x, e1 = a.y, e2 = a.z, e3 = a.w;
        bool v3ok = (ln * 4 + 3 < DOUT);
        if (!act)       { e0 = e1 = e2 = e3 = -INFINITY; }
        else if (!v3ok) { e3 = -INFINITY; }

        float m = fmaxf(fmaxf(e0, e1), fmaxf(e2, e3));
#pragma unroll
        for (int off = 8; off; off >>= 1)
            m = fmaxf(m, __shfl_xor_sync(0xFFFFFFFFu, m, off));

        float s = 0.f;
        if (act) {
            s = expf(e0 - m) + expf(e1 - m) + expf(e2 - m);
            if (v3ok) s += expf(e3 - m);
        }
#pragma unroll
        for (int off = 8; off; off >>= 1)
            s += __shfl_xor_sync(0xFFFFFFFFu, s, off);

        float lse = m + logf(s);
        if (act) {
            size_t o = (size_t)n * DOUT + ln * 4;
            outp[o]     = e0 - lse;
            outp[o + 1] = e1 - lse;
            outp[o + 2] = e2 - lse;
            if (v3ok) outp[o + 3] = e3 - lse;
        }
    }
}

// ---------------------------------------------------------------------------
extern "C" void kernel_launch(void* const* d_in, const int* in_sizes, int n_in,
                              void* d_out, int out_size) {
    const float* x  = (const float*)d_in[0];
    const void*  ei = d_in[1];
    const float* W1 = (const float*)d_in[2];
    const float* b1 = (const float*)d_in[3];
    const float* W2 = (const float*)d_in[4];
    const float* b2 = (const float*)d_in[5];
    const float* W3 = (const float*)d_in[6];
    const float* b3 = (const float*)d_in[7];
    float* out = (float*)d_out;

    float *h_ptr, *agg_ptr;
    cudaGetSymbolAddress((void**)&h_ptr, g_h);
    cudaGetSymbolAddress((void**)&agg_ptr, g_agg);

    const int SM64 = (128 * 17 + 64 * 16) * 16;  // 51200
    const int SM48 = (128 * 17 + 64 * 12) * 16;  // 47104

    static cudaStream_t s2 = nullptr;
    static cudaEvent_t evFork = nullptr, evJoin = nullptr;
    if (!s2) {
        cudaFuncSetAttribute(gemm_kernel<64>,
                             cudaFuncAttributeMaxDynamicSharedMemorySize, SM64);
        cudaFuncSetAttribute(gemm_kernel<48>,
                             cudaFuncAttributeMaxDynamicSharedMemorySize, SM48);
        cudaStreamCreateWithFlags(&s2, cudaStreamNonBlocking);
        cudaEventCreateWithFlags(&evFork, cudaEventDisableTiming);
        cudaEventCreateWithFlags(&evJoin, cudaEventDisableTiming);
    }

    const int GEMM_BLKS = (NN + 127) / 128;                    // 782
    const int EDGE_BLKS = (EE + 255) / 256;                    // 3125
    const int NODE_BLKS = (NN + 255) / 256;                    // 391
    const int GATH_BLKS = ((long long)NN * 16 + 255) / 256;    // 6250

    // --- Fork: bucket build on s2, concurrent with layer-1 GEMM ---
    cudaEventRecord(evFork, 0);
    cudaStreamWaitEvent(s2, evFork, 0);

    zero_detect_kernel<<<NODE_BLKS, 256, 0, s2>>>(ei);
    bucket_fill_kernel<<<EDGE_BLKS, 256, 0, s2>>>(ei);
    cudaEventRecord(evJoin, s2);

    gemm_kernel<64><<<GEMM_BLKS, 256, SM64>>>(x, W1, h_ptr, 64);

    cudaStreamWaitEvent(0, evJoin, 0);

    // Layer 1 aggregate: a1 = relu(gather(g1) + b1)
    gather_kernel<16, false><<<GATH_BLKS, 256>>>(h_ptr, b1, 64, agg_ptr);
    // Layer 2: g2 = a1 @ W2 ; a2 = relu(gather(g2) + b2)
    gemm_kernel<64><<<GEMM_BLKS, 256, SM64>>>(agg_ptr, W2, h_ptr, 64);
    gather_kernel<16, false><<<GATH_BLKS, 256>>>(h_ptr, b2, 64, agg_ptr);
    // Layer 3: g3 = a2 @ W3 (48-wide) ; out = log_softmax(gather(g3) + b3)
    gemm_kernel<48><<<GEMM_BLKS, 256, SM48>>>(agg_ptr, W3, h_ptr, 47);
    gather_kernel<12, true><<<GATH_BLKS, 256>>>(h_ptr, b3, 47, out);
}

// round 6
// speedup vs baseline: 1.1543x; 1.1543x over previous
#include <cuda_runtime.h>
#include <math.h>

#define NN 100000
#define EE 800000
#define DOUT 47
#define BCAP 64

// Scratch (allocation-free rule: static device globals)
__device__ float g_h[(size_t)NN * 64];
__device__ float g_agg[(size_t)NN * 64];
__device__ int   g_deg[NN];
__device__ int   g_bkt[(size_t)NN * BCAP];
__device__ int   g_idx64;

// ---------------------------------------------------------------------------
// Packed fp32x2 FMA (Blackwell FFMA2 — only reachable via PTX)
// ---------------------------------------------------------------------------
__device__ __forceinline__ void ffma2(unsigned long long& acc,
                                      unsigned long long a,
                                      unsigned long long b) {
    asm("fma.rn.f32x2 %0, %1, %2, %0;" : "+l"(acc) : "l"(a), "l"(b));
}
__device__ __forceinline__ unsigned long long pack2(float x) {
    unsigned long long r;
    asm("mov.b64 %0, {%1, %2};" : "=l"(r) : "f"(x), "f"(x));
    return r;
}

// ---------------------------------------------------------------------------
// zero degree array + (block 0) detect edge_index dtype (int64 vs int32)
// ---------------------------------------------------------------------------
__global__ void zero_detect_kernel(const void* ei) {
    int i = blockIdx.x * blockDim.x + threadIdx.x;
    if (i < NN) g_deg[i] = 0;
    if (blockIdx.x == 0) {
        __shared__ int bad;
        if (threadIdx.x == 0) bad = 0;
        __syncthreads();
        const long long* p = (const long long*)ei;
        for (int j = threadIdx.x; j < 4096; j += blockDim.x) {
            long long v = p[j];
            if (v < 0 || v >= NN) bad = 1;
        }
        __syncthreads();
        if (threadIdx.x == 0) g_idx64 = bad ? 0 : 1;
    }
}

// ---------------------------------------------------------------------------
// Bucket fill: bkt[dst][pos++] = src
// ---------------------------------------------------------------------------
__global__ void bucket_fill_kernel(const void* ei) {
    int e = blockIdx.x * blockDim.x + threadIdx.x;
    if (e >= EE) return;
    int src, dst;
    if (g_idx64) {
        const long long* p = (const long long*)ei;
        src = (int)p[e];
        dst = (int)p[EE + e];
    } else {
        const int* p = (const int*)ei;
        src = p[e];
        dst = p[EE + e];
    }
    int pos = atomicAdd(&g_deg[dst], 1);
    if (pos < BCAP) g_bkt[(size_t)dst * BCAP + pos] = src;
}

// ---------------------------------------------------------------------------
// Phase-2 mini-GEMM: out[row0..row0+256, 0..DP) = xs[256,64] @ ws[64,DP]
// 256 threads: thread (rg = tid>>3, cg = tid&7) computes 8 rows x CT cols.
// xs row-major stride 68 (scalar broadcast reads); W pairs via FFMA2.
// ---------------------------------------------------------------------------
template <int CT>   // 8 (DP=64) or 6 (DP=48)
__device__ __forceinline__ void phase2(const float* xs, const float* ws,
                                       float* out, int row0) {
    constexpr int DP = 8 * CT;
    constexpr int CP = CT / 2;
    const int tid = threadIdx.x;
    const int rg = tid >> 3, cg = tid & 7;

    unsigned long long acc[8][CP];
#pragma unroll
    for (int m = 0; m < 8; m++)
#pragma unroll
        for (int p = 0; p < CP; p++) acc[m][p] = 0ULL;

#pragma unroll 4
    for (int k = 0; k < 64; k++) {
        unsigned long long xp[8];
#pragma unroll
        for (int m = 0; m < 8; m++)
            xp[m] = pack2(xs[(rg + 32 * m) * 68 + k]);
        const unsigned long long* wp =
            (const unsigned long long*)&ws[k * DP + cg * CT];
        unsigned long long wv[CP];
#pragma unroll
        for (int p = 0; p < CP; p++) wv[p] = wp[p];
#pragma unroll
        for (int m = 0; m < 8; m++)
#pragma unroll
            for (int p = 0; p < CP; p++) ffma2(acc[m][p], xp[m], wv[p]);
    }

#pragma unroll
    for (int m = 0; m < 8; m++) {
        int gr = row0 + rg + 32 * m;
        if (gr < NN) {
            unsigned long long* o =
                (unsigned long long*)(out + (size_t)gr * DP + cg * CT);
#pragma unroll
            for (int p = 0; p < CP; p++) o[p] = acc[m][p];
        }
    }
}

// Stage W[64, wcols] into smem zero-padded to [64, DP]
template <int DP>
__device__ __forceinline__ void stage_w(float* ws, const float* __restrict__ W,
                                        int wcols) {
    for (int i = threadIdx.x; i < 64 * DP; i += 256) {
        int k = i / DP, c = i - k * DP;
        ws[i] = (c < wcols) ? W[k * wcols + c] : 0.f;
    }
}

// ---------------------------------------------------------------------------
// Standalone GEMM: stage 256 x-rows from global, then phase2.
// blk_base allows split launches (row0 = (blockIdx.x + blk_base) * 256).
// ---------------------------------------------------------------------------
template <int CT>   // 8 (DP=64) or 6 (DP=48)
__global__ void gemm_kernel(const float* __restrict__ in,
                            const float* __restrict__ W, int wcols,
                            float* __restrict__ out, int blk_base) {
    constexpr int DP = 8 * CT;
    extern __shared__ float smem[];
    float* xs = smem;                // 256 rows x stride 68
    float* ws = smem + 256 * 68;     // 64 x DP

    stage_w<DP>(ws, W, wcols);
    const int row0 = (blockIdx.x + blk_base) * 256;
    for (int i = threadIdx.x; i < 256 * 16; i += 256) {
        int r = i >> 4, c4 = i & 15;
        int gr = row0 + r;
        float4 v = (gr < NN) ? ((const float4*)in)[(size_t)gr * 16 + c4]
                             : make_float4(0.f, 0.f, 0.f, 0.f);
        *(float4*)&xs[r * 68 + c4 * 4] = v;
    }
    __syncthreads();
    phase2<CT>(xs, ws, out, row0);
}

// ---------------------------------------------------------------------------
// Gather: out[n] = epilogue(bias + sum_{e in bkt[n]} h[src[e]]).
// 16 lanes per node, lane = one float4 chunk. Indices front-batched via int4
// loads (MLP ~8-10). Epilogue: ReLU store, or fused log_softmax (LSM).
// ---------------------------------------------------------------------------
template <int CH, bool LSM>
__global__ void gather_kernel(const float* __restrict__ h,
                              const float* __restrict__ bias, int bcols,
                              float* __restrict__ outp) {
    int t = blockIdx.x * blockDim.x + threadIdx.x;
    int n = t >> 4;
    int ln = t & 15;
    if (n >= NN) return;

    const bool act = (ln < CH);
    float4 a = make_float4(0.f, 0.f, 0.f, 0.f);
    float4 b = a;
    if (act) {
        int c = ln * 4;
        a.x = bias[c];
        a.y = bias[c + 1];
        a.z = bias[c + 2];
        a.w = (c + 3 < bcols) ? bias[c + 3] : 0.f;
    }

    int deg = min(g_deg[n], BCAP);
    const int* bp = &g_bkt[(size_t)n * BCAP];
    const float4* h4 = (const float4*)h;

    int e = 0;
    for (; e + 8 <= deg; e += 8) {
        int4 i0 = *(const int4*)(bp + e);
        int4 i1 = *(const int4*)(bp + e + 4);
        if (act) {
            float4 v0 = h4[(size_t)i0.x * CH + ln];
            float4 v1 = h4[(size_t)i0.y * CH + ln];
            float4 v2 = h4[(size_t)i0.z * CH + ln];
            float4 v3 = h4[(size_t)i0.w * CH + ln];
            float4 v4 = h4[(size_t)i1.x * CH + ln];
            float4 v5 = h4[(size_t)i1.y * CH + ln];
            float4 v6 = h4[(size_t)i1.z * CH + ln];
            float4 v7 = h4[(size_t)i1.w * CH + ln];
            a.x += (v0.x + v1.x) + (v2.x + v3.x);
            a.y += (v0.y + v1.y) + (v2.y + v3.y);
            a.z += (v0.z + v1.z) + (v2.z + v3.z);
            a.w += (v0.w + v1.w) + (v2.w + v3.w);
            b.x += (v4.x + v5.x) + (v6.x + v7.x);
            b.y += (v4.y + v5.y) + (v6.y + v7.y);
            b.z += (v4.z + v5.z) + (v6.z + v7.z);
            b.w += (v4.w + v5.w) + (v6.w + v7.w);
        }
    }
    if (e + 4 <= deg) {
        int4 i0 = *(const int4*)(bp + e);
        if (act) {
            float4 v0 = h4[(size_t)i0.x * CH + ln];
            float4 v1 = h4[(size_t)i0.y * CH + ln];
            float4 v2 = h4[(size_t)i0.z * CH + ln];
            float4 v3 = h4[(size_t)i0.w * CH + ln];
            a.x += (v0.x + v1.x) + (v2.x + v3.x);
            a.y += (v0.y + v1.y) + (v2.y + v3.y);
            a.z += (v0.z + v1.z) + (v2.z + v3.z);
            a.w += (v0.w + v1.w) + (v2.w + v3.w);
        }
        e += 4;
    }
    {
        int r = deg - e;
        int s0 = (r > 0) ? bp[e]     : 0;
        int s1 = (r > 1) ? bp[e + 1] : 0;
        int s2 = (r > 2) ? bp[e + 2] : 0;
        if (act) {
            if (r > 0) {
                float4 v = h4[(size_t)s0 * CH + ln];
                a.x += v.x; a.y += v.y; a.z += v.z; a.w += v.w;
            }
            if (r > 1) {
                float4 v = h4[(size_t)s1 * CH + ln];
                b.x += v.x; b.y += v.y; b.z += v.z; b.w += v.w;
            }
            if (r > 2) {
                float4 v = h4[(size_t)s2 * CH + ln];
                a.x += v.x; a.y += v.y; a.z += v.z; a.w += v.w;
            }
        }
    }
    a.x += b.x; a.y += b.y; a.z += b.z; a.w += b.w;

    if (!LSM) {
        a.x = fmaxf(a.x, 0.f); a.y = fmaxf(a.y, 0.f);
        a.z = fmaxf(a.z, 0.f); a.w = fmaxf(a.w, 0.f);
        if (act) ((float4*)outp)[(size_t)n * CH + ln] = a;
    } else {
        float e0 = a.x, e1 = a.y, e2 = a.z, e3 = a.w;
        bool v3ok = (ln * 4 + 3 < DOUT);
        if (!act)       { e0 = e1 = e2 = e3 = -INFINITY; }
        else if (!v3ok) { e3 = -INFINITY; }

        float m = fmaxf(fmaxf(e0, e1), fmaxf(e2, e3));
#pragma unroll
        for (int off = 8; off; off >>= 1)
            m = fmaxf(m, __shfl_xor_sync(0xFFFFFFFFu, m, off));

        float s = 0.f;
        if (act) {
            s = expf(e0 - m) + expf(e1 - m) + expf(e2 - m);
            if (v3ok) s += expf(e3 - m);
        }
#pragma unroll
        for (int off = 8; off; off >>= 1)
            s += __shfl_xor_sync(0xFFFFFFFFu, s, off);

        float lse = m + logf(s);
        if (act) {
            size_t o = (size_t)n * DOUT + ln * 4;
            outp[o]     = e0 - lse;
            outp[o + 1] = e1 - lse;
            outp[o + 2] = e2 - lse;
            if (v3ok) outp[o + 3] = e3 - lse;
        }
    }
}

// ---------------------------------------------------------------------------
extern "C" void kernel_launch(void* const* d_in, const int* in_sizes, int n_in,
                              void* d_out, int out_size) {
    const float* x  = (const float*)d_in[0];
    const void*  ei = d_in[1];
    const float* W1 = (const float*)d_in[2];
    const float* b1 = (const float*)d_in[3];
    const float* W2 = (const float*)d_in[4];
    const float* b2 = (const float*)d_in[5];
    const float* W3 = (const float*)d_in[6];
    const float* b3 = (const float*)d_in[7];
    float* out = (float*)d_out;

    float *h_ptr, *agg_ptr;
    cudaGetSymbolAddress((void**)&h_ptr, g_h);
    cudaGetSymbolAddress((void**)&agg_ptr, g_agg);

    const int SM64 = (256 * 68 + 64 * 64) * 4;  // 86016
    const int SM48 = (256 * 68 + 64 * 48) * 4;  // 81920

    static cudaStream_t s2 = nullptr;
    static cudaEvent_t evFork = nullptr, evJoin = nullptr;
    if (!s2) {
        cudaFuncSetAttribute(gemm_kernel<8>,
                             cudaFuncAttributeMaxDynamicSharedMemorySize, SM64);
        cudaFuncSetAttribute(gemm_kernel<6>,
                             cudaFuncAttributeMaxDynamicSharedMemorySize, SM48);
        cudaStreamCreateWithFlags(&s2, cudaStreamNonBlocking);
        cudaEventCreateWithFlags(&evFork, cudaEventDisableTiming);
        cudaEventCreateWithFlags(&evJoin, cudaEventDisableTiming);
    }

    const int GEMM_BLKS = (NN + 255) / 256;                    // 391
    const int HALF_A    = (GEMM_BLKS + 1) / 2;                 // 196
    const int HALF_B    = GEMM_BLKS - HALF_A;                  // 195
    const int EDGE_BLKS = (EE + 255) / 256;                    // 3125
    const int NODE_BLKS = (NN + 255) / 256;                    // 391
    const int GATH_BLKS = ((long long)NN * 16 + 255) / 256;    // 6250

    // --- Fork: bucket build on s2, concurrent with layer-1 GEMM ---
    cudaEventRecord(evFork, 0);
    cudaStreamWaitEvent(s2, evFork, 0);

    zero_detect_kernel<<<NODE_BLKS, 256, 0, s2>>>(ei);           // launch 1
    bucket_fill_kernel<<<EDGE_BLKS, 256, 0, s2>>>(ei);           // launch 2
    cudaEventRecord(evJoin, s2);

    // Layer-1 GEMM on the main stream
    gemm_kernel<8><<<GEMM_BLKS, 256, SM64>>>(x, W1, 64, h_ptr, 0);   // 3

    cudaStreamWaitEvent(0, evJoin, 0);

    // Layer 1 aggregate
    gather_kernel<16, false><<<GATH_BLKS, 256>>>(h_ptr, b1, 64, agg_ptr); // 4
    // Layer 2 GEMM split in two so ncu (-s 5 -c 1) captures gemm2b
    gemm_kernel<8><<<HALF_A, 256, SM64>>>(agg_ptr, W2, 64, h_ptr, 0);      // 5
    gemm_kernel<8><<<HALF_B, 256, SM64>>>(agg_ptr, W2, 64, h_ptr, HALF_A); // 6
    gather_kernel<16, false><<<GATH_BLKS, 256>>>(h_ptr, b2, 64, agg_ptr);  // 7
    // Layer 3
    gemm_kernel<6><<<GEMM_BLKS, 256, SM48>>>(agg_ptr, W3, 47, h_ptr, 0);   // 8
    gather_kernel<12, true><<<GATH_BLKS, 256>>>(h_ptr, b3, 47, out);       // 9
}